// round 4
// baseline (speedup 1.0000x reference)
#include <cuda_runtime.h>
#include <cstdint>

#define CIN 3
#define COUT 16
#define HH 32
#define WW 32
#define OH 30
#define OW 30

typedef unsigned long long u64;

// ---- f32x2 packed-math helpers (SASS FFMA2 via PTX only) ----
__device__ __forceinline__ u64 pk2(float a, float b) {
    u64 r;
    asm("mov.b64 %0, {%1, %2};" : "=l"(r) : "f"(a), "f"(b));
    return r;
}
__device__ __forceinline__ u64 fma2(u64 a, u64 b, u64 c) {
    u64 d;
    asm("fma.rn.f32x2 %0, %1, %2, %3;" : "=l"(d) : "l"(a), "l"(b), "l"(c));
    return d;
}
__device__ __forceinline__ void upk2(u64 v, float& a, float& b) {
    asm("mov.b64 {%0, %1}, %2;" : "=f"(a), "=f"(b) : "l"(v));
}

// activation: relu(v) * min(v+3,6)/6 == max(v,0) * min(v*(1/6)+0.5, 1)
__device__ __forceinline__ float hswish_relu(float v) {
    return fmaxf(v, 0.0f) * fminf(v * (1.0f / 6.0f) + 0.5f, 1.0f);
}

// One block = one image. 8 warps; warp w -> output channels (2w, 2w+1) packed
// in one f32x2 lane. Lane = output column (30 active).
//
// R4: image lives in smem PRE-DUPLICATED as {v,v} pairs, so each window value
// is a single LDS.64 straight into an FFMA2-ready register pair (no pack MOVs,
// no copy MOVs: double-buffered row registers with compile-time parity).
// Streaming over input rows: row r contributes to output accumulators
// r (ky0), r-1 (ky1), r-2 (ky2); row r+1 is prefetched a full iteration ahead.
// Fully unrolled 32-iteration pipeline.
__global__ void __launch_bounds__(256, 2) conv3x3_hswish_kernel(
    const float* __restrict__ x,
    const float* __restrict__ wgt,
    const float* __restrict__ bias,
    float* __restrict__ out)
{
    __shared__ u64 s_in[CIN * HH * WW];  // dup pairs, 24 KB

    const int n   = blockIdx.x;
    const int tid = threadIdx.x;

    {   // coalesced load + duplication: 768 float4 in -> 1536 float4 out
        const float4* src = reinterpret_cast<const float4*>(x + (size_t)n * (CIN * HH * WW));
        float4* dst = reinterpret_cast<float4*>(s_in);
        #pragma unroll
        for (int i = 0; i < 3; i++) {
            const int idx = tid + i * 256;
            float4 f = src[idx];
            dst[idx * 2 + 0] = make_float4(f.x, f.x, f.y, f.y);
            dst[idx * 2 + 1] = make_float4(f.z, f.z, f.w, f.w);
        }
    }
    __syncthreads();

    const int warp = tid >> 5;
    const int lane = tid & 31;
    const int c0   = warp * 2;

    // packed weights: wp[ci*9 + ky*3 + kx] = {w[c0], w[c0+1]}
    u64 wp[27];
    #pragma unroll
    for (int t = 0; t < 27; t++)
        wp[t] = pk2(wgt[c0 * 27 + t], wgt[(c0 + 1) * 27 + t]);
    const u64 bp = pk2(bias[c0], bias[c0 + 1]);

    if (lane >= OW) return;  // all barriers done; safe to retire

    const u64* base = s_in + lane;   // [ci*1024 + row*32 + kx]
    float* out0 = out + ((size_t)n * COUT + c0) * (OH * OW) + lane;

    // Double-buffered current-row window (dup pairs). Parity selected at
    // compile time inside the fully unrolled loop -> no copies.
    u64 b0[9], b1[9];
    u64 acc[3];   // acc[y % 3] = accumulator for output row y

    // preload input row 0 into b0
    #pragma unroll
    for (int ci = 0; ci < CIN; ci++)
        #pragma unroll
        for (int kx = 0; kx < 3; kx++)
            b0[ci * 3 + kx] = base[ci * 1024 + kx];

    #pragma unroll
    for (int r = 0; r < 32; r++) {
        // prefetch input row r+1 into the other buffer
        if (r < 31) {
            #pragma unroll
            for (int ci = 0; ci < CIN; ci++)
                #pragma unroll
                for (int kx = 0; kx < 3; kx++) {
                    u64 v = base[ci * 1024 + (r + 1) * 32 + kx];
                    if (r & 1) b0[ci * 3 + kx] = v; else b1[ci * 3 + kx] = v;
                }
        }

        if (r <= 29) acc[r % 3] = bp;

        #pragma unroll
        for (int t = 0; t < 9; t++) {
            const int ci = t / 3, kx = t % 3;
            const u64 cv = (r & 1) ? b1[t] : b0[t];
            if (r >= 2)            acc[(r - 2) % 3] = fma2(cv, wp[ci * 9 + 6 + kx], acc[(r - 2) % 3]);
            if (r >= 1 && r <= 30) acc[(r - 1) % 3] = fma2(cv, wp[ci * 9 + 3 + kx], acc[(r - 1) % 3]);
            if (r <= 29)           acc[r % 3]       = fma2(cv, wp[ci * 9 + 0 + kx], acc[r % 3]);
        }

        // output row y = r-2 is complete
        if (r >= 2) {
            float v0, v1;
            upk2(acc[(r - 2) % 3], v0, v1);
            const int yoff = (r - 2) * OW;
            out0[yoff]           = hswish_relu(v0);
            out0[OH * OW + yoff] = hswish_relu(v1);
        }
    }
}

extern "C" void kernel_launch(void* const* d_in, const int* in_sizes, int n_in,
                              void* d_out, int out_size) {
    const float* x = (const float*)d_in[0];
    const float* w = (const float*)d_in[1];
    const float* b = (const float*)d_in[2];
    float* out = (float*)d_out;

    const int N = in_sizes[0] / (CIN * HH * WW);  // 4096
    conv3x3_hswish_kernel<<<N, 256>>>(x, w, b, out);
}

// round 5
// speedup vs baseline: 1.1487x; 1.1487x over previous
#include <cuda_runtime.h>
#include <cstdint>

#define CIN 3
#define COUT 16
#define HH 32
#define WW 32
#define OH 30
#define OW 30

typedef unsigned long long u64;

// ---- f32x2 packed-math helpers (SASS FFMA2 via PTX only) ----
__device__ __forceinline__ u64 pk2(float a, float b) {
    u64 r;
    asm("mov.b64 %0, {%1, %2};" : "=l"(r) : "f"(a), "f"(b));
    return r;
}
__device__ __forceinline__ u64 dup2(float a) {
    u64 r;
    asm("mov.b64 %0, {%1, %1};" : "=l"(r) : "f"(a));
    return r;
}
__device__ __forceinline__ u64 fma2(u64 a, u64 b, u64 c) {
    u64 d;
    asm("fma.rn.f32x2 %0, %1, %2, %3;" : "=l"(d) : "l"(a), "l"(b), "l"(c));
    return d;
}
__device__ __forceinline__ void upk2(u64 v, float& a, float& b) {
    asm("mov.b64 {%0, %1}, %2;" : "=f"(a), "=f"(b) : "l"(v));
}

// activation: relu(v) * min(v+3,6)/6 == max(v,0) * min(v*(1/6)+0.5, 1)
__device__ __forceinline__ float hswish_relu(float v) {
    return fmaxf(v, 0.0f) * fminf(v * (1.0f / 6.0f) + 0.5f, 1.0f);
}

// One block = one image, 128 threads = 4 warps. Warp w computes FOUR output
// channels (4w..4w+3) as two f32x2 accumulator sets, so each loaded input
// value (scalar LDS.32 + one dup MOV) feeds 6 FFMA2 — the fma pipe, not the
// issue pipe, is the binding resource.
//
// Streaming over input rows r: row r contributes to output rows r (ky0),
// r-1 (ky1), r-2 (ky2). Row r+1 is prefetched a full iteration ahead into a
// parity-selected scalar double buffer (no copy MOVs). Fully unrolled.
__global__ void __launch_bounds__(128, 3) conv3x3_hswish_kernel(
    const float* __restrict__ x,
    const float* __restrict__ wgt,
    const float* __restrict__ bias,
    float* __restrict__ out)
{
    __shared__ float s_in[CIN * HH * WW];  // 12 KB

    const int n   = blockIdx.x;
    const int tid = threadIdx.x;

    {   // coalesced image load: 768 float4 / 128 threads = 6 each
        const float4* src = reinterpret_cast<const float4*>(x + (size_t)n * (CIN * HH * WW));
        float4* dst = reinterpret_cast<float4*>(s_in);
        #pragma unroll
        for (int i = 0; i < 6; i++) dst[tid + i * 128] = src[tid + i * 128];
    }
    __syncthreads();

    const int warp = tid >> 5;
    const int lane = tid & 31;
    const int c0   = warp * 4;   // four channels c0..c0+3

    // packed weights: two pairs. wpA -> channels (c0, c0+1), wpB -> (c0+2, c0+3)
    u64 wpA[27], wpB[27];
    #pragma unroll
    for (int t = 0; t < 27; t++) {
        wpA[t] = pk2(wgt[(c0 + 0) * 27 + t], wgt[(c0 + 1) * 27 + t]);
        wpB[t] = pk2(wgt[(c0 + 2) * 27 + t], wgt[(c0 + 3) * 27 + t]);
    }
    const u64 bpA = pk2(bias[c0 + 0], bias[c0 + 1]);
    const u64 bpB = pk2(bias[c0 + 2], bias[c0 + 3]);

    if (lane >= OW) return;  // barrier already done; safe to retire

    const float* base = s_in + lane;   // [ci*1024 + row*32 + kx]
    float* out0 = out + ((size_t)n * COUT + c0) * (OH * OW) + lane;

    // scalar double-buffered row window; parity is compile-time in the
    // fully unrolled loop (no copies).
    float nb0[9], nb1[9];
    u64 accA[3], accB[3];   // acc[y % 3] = accumulator for output row y

    #pragma unroll
    for (int ci = 0; ci < CIN; ci++)
        #pragma unroll
        for (int kx = 0; kx < 3; kx++)
            nb0[ci * 3 + kx] = base[ci * 1024 + kx];   // row 0

    #pragma unroll
    for (int r = 0; r < 32; r++) {
        // prefetch input row r+1 into the other buffer
        if (r < 31) {
            #pragma unroll
            for (int ci = 0; ci < CIN; ci++)
                #pragma unroll
                for (int kx = 0; kx < 3; kx++) {
                    float v = base[ci * 1024 + (r + 1) * 32 + kx];
                    if (r & 1) nb0[ci * 3 + kx] = v; else nb1[ci * 3 + kx] = v;
                }
        }

        if (r <= 29) { accA[r % 3] = bpA; accB[r % 3] = bpB; }

        #pragma unroll
        for (int t = 0; t < 9; t++) {
            const int ci = t / 3, kx = t % 3;
            const u64 dv = dup2((r & 1) ? nb1[t] : nb0[t]);  // one dup, 6 uses
            if (r >= 2) {
                accA[(r - 2) % 3] = fma2(dv, wpA[ci * 9 + 6 + kx], accA[(r - 2) % 3]);
                accB[(r - 2) % 3] = fma2(dv, wpB[ci * 9 + 6 + kx], accB[(r - 2) % 3]);
            }
            if (r >= 1 && r <= 30) {
                accA[(r - 1) % 3] = fma2(dv, wpA[ci * 9 + 3 + kx], accA[(r - 1) % 3]);
                accB[(r - 1) % 3] = fma2(dv, wpB[ci * 9 + 3 + kx], accB[(r - 1) % 3]);
            }
            if (r <= 29) {
                accA[r % 3] = fma2(dv, wpA[ci * 9 + 0 + kx], accA[r % 3]);
                accB[r % 3] = fma2(dv, wpB[ci * 9 + 0 + kx], accB[r % 3]);
            }
        }

        // output row y = r-2 is complete for all 4 channels
        if (r >= 2) {
            const int yoff = (r - 2) * OW;
            float v0, v1, v2, v3;
            upk2(accA[(r - 2) % 3], v0, v1);
            upk2(accB[(r - 2) % 3], v2, v3);
            out0[0 * OH * OW + yoff] = hswish_relu(v0);
            out0[1 * OH * OW + yoff] = hswish_relu(v1);
            out0[2 * OH * OW + yoff] = hswish_relu(v2);
            out0[3 * OH * OW + yoff] = hswish_relu(v3);
        }
    }
}

extern "C" void kernel_launch(void* const* d_in, const int* in_sizes, int n_in,
                              void* d_out, int out_size) {
    const float* x = (const float*)d_in[0];
    const float* w = (const float*)d_in[1];
    const float* b = (const float*)d_in[2];
    float* out = (float*)d_out;

    const int N = in_sizes[0] / (CIN * HH * WW);  // 4096
    conv3x3_hswish_kernel<<<N, 128>>>(x, w, b, out);
}